// round 2
// baseline (speedup 1.0000x reference)
#include <cuda_runtime.h>

// Problem constants (fixed by the reference)
#define BATCH 512
#define SEQ   256
#define HID   768
#define NCLS  2

// Scratch for pooled features [BATCH, 2*HID] (device global: allocation-free)
__device__ float g_pooled[BATCH * 2 * HID];

// One CTA per (batch, half). 192 threads, each owns one float4 (4 features).
// half=0 -> (x1, m1) -> pooled cols [0,768); half=1 -> (x2, m2) -> cols [768,1536).
__global__ __launch_bounds__(192) void pool_kernel(
    const float* __restrict__ x1, const float* __restrict__ x2,
    const int*   __restrict__ m1, const int*   __restrict__ m2)
{
    const int b    = blockIdx.x;
    const int half = blockIdx.y;
    const int t    = threadIdx.x;  // 0..191

    const float* __restrict__ x = half ? x2 : x1;
    const int*   __restrict__ m = half ? m2 : m1;

    // ---- effective length: index of first 0 in mask row; none (or idx 0) -> SEQ.
    // Warp 0 scans all 256 mask entries via ballots: exact, no tree reduction.
    __shared__ int s_eff;
    if (t < 32) {
        int first_zero = SEQ;  // sentinel: no zero found
        #pragma unroll
        for (int chunk = 0; chunk < SEQ / 32; chunk++) {
            int v = m[b * SEQ + chunk * 32 + t];
            unsigned zeros = __ballot_sync(0xffffffffu, v == 0);
            if (zeros != 0u) {
                first_zero = chunk * 32 + (__ffs(zeros) - 1);
                break;
            }
        }
        // All lanes that didn't break have first_zero from their own chunk or SEQ;
        // lanes exit the loop at different chunks, so take warp-min.
        #pragma unroll
        for (int off = 16; off > 0; off >>= 1)
            first_zero = min(first_zero, __shfl_down_sync(0xffffffffu, first_zero, off));
        if (t == 0) {
            // first_zero == 0 can't occur (lengths >= 1) but handle per reference:
            s_eff = (first_zero == 0 || first_zero == SEQ) ? SEQ : first_zero;
        }
    }
    __syncthreads();
    const int eff = s_eff;

    // ---- streaming masked max over s in [0, eff) ----
    const float4* __restrict__ xp =
        reinterpret_cast<const float4*>(x + (size_t)b * SEQ * HID) + t;
    const int STRIDE4 = HID / 4;  // 192 float4 per s-row

    const float NEG = __int_as_float(0xff800000);  // -inf
    float4 a0 = make_float4(NEG, NEG, NEG, NEG);
    float4 a1 = a0, a2 = a0, a3 = a0;

    const int s4 = eff & ~3;
    int s = 0;
    for (; s < s4; s += 4) {
        float4 v0 = xp[(size_t)(s + 0) * STRIDE4];
        float4 v1 = xp[(size_t)(s + 1) * STRIDE4];
        float4 v2 = xp[(size_t)(s + 2) * STRIDE4];
        float4 v3 = xp[(size_t)(s + 3) * STRIDE4];
        a0.x = fmaxf(a0.x, v0.x); a0.y = fmaxf(a0.y, v0.y);
        a0.z = fmaxf(a0.z, v0.z); a0.w = fmaxf(a0.w, v0.w);
        a1.x = fmaxf(a1.x, v1.x); a1.y = fmaxf(a1.y, v1.y);
        a1.z = fmaxf(a1.z, v1.z); a1.w = fmaxf(a1.w, v1.w);
        a2.x = fmaxf(a2.x, v2.x); a2.y = fmaxf(a2.y, v2.y);
        a2.z = fmaxf(a2.z, v2.z); a2.w = fmaxf(a2.w, v2.w);
        a3.x = fmaxf(a3.x, v3.x); a3.y = fmaxf(a3.y, v3.y);
        a3.z = fmaxf(a3.z, v3.z); a3.w = fmaxf(a3.w, v3.w);
    }
    for (; s < eff; s++) {
        float4 v0 = xp[(size_t)s * STRIDE4];
        a0.x = fmaxf(a0.x, v0.x); a0.y = fmaxf(a0.y, v0.y);
        a0.z = fmaxf(a0.z, v0.z); a0.w = fmaxf(a0.w, v0.w);
    }
    a0.x = fmaxf(fmaxf(a0.x, a1.x), fmaxf(a2.x, a3.x));
    a0.y = fmaxf(fmaxf(a0.y, a1.y), fmaxf(a2.y, a3.y));
    a0.z = fmaxf(fmaxf(a0.z, a1.z), fmaxf(a2.z, a3.z));
    a0.w = fmaxf(fmaxf(a0.w, a1.w), fmaxf(a2.w, a3.w));

    float4* __restrict__ outp =
        reinterpret_cast<float4*>(g_pooled + (size_t)b * (2 * HID) + half * HID) + t;
    *outp = a0;
}

// One CTA per batch row: out[b, c] = sum_h pooled[b, h] * W[c, h] + bias[c]
__global__ __launch_bounds__(256) void gemv_kernel(
    const float* __restrict__ W, const float* __restrict__ bias,
    float* __restrict__ out)
{
    const int b = blockIdx.x;
    const int t = threadIdx.x;  // 0..255
    const float* __restrict__ p = g_pooled + (size_t)b * (2 * HID);

    float acc0 = 0.f, acc1 = 0.f;
    #pragma unroll
    for (int h = t; h < 2 * HID; h += 256) {
        float v = p[h];
        acc0 += v * W[h];
        acc1 += v * W[2 * HID + h];
    }

    __shared__ float r0[256], r1[256];
    r0[t] = acc0; r1[t] = acc1;
    __syncthreads();
    #pragma unroll
    for (int off = 128; off > 0; off >>= 1) {
        if (t < off) { r0[t] += r0[t + off]; r1[t] += r1[t + off]; }
        __syncthreads();
    }
    if (t == 0) {
        out[b * NCLS + 0] = r0[0] + bias[0];
        out[b * NCLS + 1] = r1[0] + bias[1];
    }
}

extern "C" void kernel_launch(void* const* d_in, const int* in_sizes, int n_in,
                              void* d_out, int out_size)
{
    const float* x1 = (const float*)d_in[0];
    const float* x2 = (const float*)d_in[1];
    const int*   m1 = (const int*)  d_in[2];
    const int*   m2 = (const int*)  d_in[3];
    const float* W  = (const float*)d_in[4];
    const float* bs = (const float*)d_in[5];
    float* out = (float*)d_out;

    dim3 grid(BATCH, 2);
    pool_kernel<<<grid, 192>>>(x1, x2, m1, m2);
    gemv_kernel<<<BATCH, 256>>>(W, bs, out);
}

// round 3
// speedup vs baseline: 1.1467x; 1.1467x over previous
#include <cuda_runtime.h>

// Problem constants (fixed by the reference)
#define BATCH  512
#define SEQ    256
#define HID    768
#define NCLS   2
#define NCHUNK 4
#define CHUNK  64   // SEQ / NCHUNK

// Partial pooled maxima [BATCH][2][NCHUNK][HID] (device global: allocation-free)
__device__ float g_part[BATCH * 2 * NCHUNK * HID];

// One CTA per (batch, half, s-chunk). 192 threads, each owns one float4 (4 features).
__global__ __launch_bounds__(192) void pool_kernel(
    const float* __restrict__ x1, const float* __restrict__ x2,
    const int*   __restrict__ m1, const int*   __restrict__ m2)
{
    const int b    = blockIdx.x;
    const int half = blockIdx.y;
    const int cz   = blockIdx.z;
    const int t    = threadIdx.x;  // 0..191

    const float* __restrict__ x = half ? x2 : x1;
    const int*   __restrict__ m = half ? m2 : m1;

    // ---- effective length: index of first 0 in mask row; none (or idx 0) -> SEQ.
    __shared__ int s_eff;
    if (t < 32) {
        int first_zero = SEQ;
        #pragma unroll
        for (int chunk = 0; chunk < SEQ / 32; chunk++) {
            int v = m[b * SEQ + chunk * 32 + t];
            unsigned zeros = __ballot_sync(0xffffffffu, v == 0);
            if (zeros != 0u) {
                first_zero = chunk * 32 + (__ffs(zeros) - 1);
                break;
            }
        }
        #pragma unroll
        for (int off = 16; off > 0; off >>= 1)
            first_zero = min(first_zero, __shfl_down_sync(0xffffffffu, first_zero, off));
        if (t == 0)
            s_eff = (first_zero == 0 || first_zero == SEQ) ? SEQ : first_zero;
    }
    __syncthreads();
    const int eff = s_eff;

    float4* __restrict__ outp = reinterpret_cast<float4*>(
        g_part + (size_t)(((b * 2 + half) * NCHUNK + cz)) * HID) + t;

    const float NEG = __int_as_float(0xff800000);  // -inf
    const int s_begin = cz * CHUNK;
    const int s_end   = min(eff, s_begin + CHUNK);

    if (s_begin >= s_end) {                 // chunk entirely beyond eff
        *outp = make_float4(NEG, NEG, NEG, NEG);
        return;
    }

    const float4* __restrict__ xp =
        reinterpret_cast<const float4*>(x + (size_t)b * SEQ * HID) + t;
    const int STRIDE4 = HID / 4;  // 192 float4 per s-row

    float4 a0 = make_float4(NEG, NEG, NEG, NEG);
    float4 a1 = a0, a2 = a0, a3 = a0;

    const int n  = s_end - s_begin;
    const int n8 = n & ~7;
    int s = s_begin;
    const int stop8 = s_begin + n8;
    for (; s < stop8; s += 8) {
        float4 v0 = __ldcs(xp + (size_t)(s + 0) * STRIDE4);
        float4 v1 = __ldcs(xp + (size_t)(s + 1) * STRIDE4);
        float4 v2 = __ldcs(xp + (size_t)(s + 2) * STRIDE4);
        float4 v3 = __ldcs(xp + (size_t)(s + 3) * STRIDE4);
        float4 v4 = __ldcs(xp + (size_t)(s + 4) * STRIDE4);
        float4 v5 = __ldcs(xp + (size_t)(s + 5) * STRIDE4);
        float4 v6 = __ldcs(xp + (size_t)(s + 6) * STRIDE4);
        float4 v7 = __ldcs(xp + (size_t)(s + 7) * STRIDE4);
        a0.x = fmaxf(a0.x, fmaxf(v0.x, v4.x)); a0.y = fmaxf(a0.y, fmaxf(v0.y, v4.y));
        a0.z = fmaxf(a0.z, fmaxf(v0.z, v4.z)); a0.w = fmaxf(a0.w, fmaxf(v0.w, v4.w));
        a1.x = fmaxf(a1.x, fmaxf(v1.x, v5.x)); a1.y = fmaxf(a1.y, fmaxf(v1.y, v5.y));
        a1.z = fmaxf(a1.z, fmaxf(v1.z, v5.z)); a1.w = fmaxf(a1.w, fmaxf(v1.w, v5.w));
        a2.x = fmaxf(a2.x, fmaxf(v2.x, v6.x)); a2.y = fmaxf(a2.y, fmaxf(v2.y, v6.y));
        a2.z = fmaxf(a2.z, fmaxf(v2.z, v6.z)); a2.w = fmaxf(a2.w, fmaxf(v2.w, v6.w));
        a3.x = fmaxf(a3.x, fmaxf(v3.x, v7.x)); a3.y = fmaxf(a3.y, fmaxf(v3.y, v7.y));
        a3.z = fmaxf(a3.z, fmaxf(v3.z, v7.z)); a3.w = fmaxf(a3.w, fmaxf(v3.w, v7.w));
    }
    for (; s < s_end; s++) {
        float4 v0 = __ldcs(xp + (size_t)s * STRIDE4);
        a0.x = fmaxf(a0.x, v0.x); a0.y = fmaxf(a0.y, v0.y);
        a0.z = fmaxf(a0.z, v0.z); a0.w = fmaxf(a0.w, v0.w);
    }
    a0.x = fmaxf(fmaxf(a0.x, a1.x), fmaxf(a2.x, a3.x));
    a0.y = fmaxf(fmaxf(a0.y, a1.y), fmaxf(a2.y, a3.y));
    a0.z = fmaxf(fmaxf(a0.z, a1.z), fmaxf(a2.z, a3.z));
    a0.w = fmaxf(fmaxf(a0.w, a1.w), fmaxf(a2.w, a3.w));

    *outp = a0;
}

// One CTA per batch row: combine chunk maxima, then out[b,c] = pooled . W[c] + bias[c]
__global__ __launch_bounds__(256) void gemv_kernel(
    const float* __restrict__ W, const float* __restrict__ bias,
    float* __restrict__ out)
{
    const int b = blockIdx.x;
    const int t = threadIdx.x;  // 0..255

    float acc0 = 0.f, acc1 = 0.f;
    #pragma unroll
    for (int h = t; h < 2 * HID; h += 256) {
        const int half = h / HID;
        const int hh   = h % HID;
        const float* __restrict__ p =
            g_part + (size_t)((b * 2 + half) * NCHUNK) * HID + hh;
        float v = p[0];
        v = fmaxf(v, p[HID]);
        v = fmaxf(v, p[2 * HID]);
        v = fmaxf(v, p[3 * HID]);
        acc0 += v * W[h];
        acc1 += v * W[2 * HID + h];
    }

    __shared__ float r0[256], r1[256];
    r0[t] = acc0; r1[t] = acc1;
    __syncthreads();
    #pragma unroll
    for (int off = 128; off > 0; off >>= 1) {
        if (t < off) { r0[t] += r0[t + off]; r1[t] += r1[t + off]; }
        __syncthreads();
    }
    if (t == 0) {
        out[b * NCLS + 0] = r0[0] + bias[0];
        out[b * NCLS + 1] = r1[0] + bias[1];
    }
}

extern "C" void kernel_launch(void* const* d_in, const int* in_sizes, int n_in,
                              void* d_out, int out_size)
{
    const float* x1 = (const float*)d_in[0];
    const float* x2 = (const float*)d_in[1];
    const int*   m1 = (const int*)  d_in[2];
    const int*   m2 = (const int*)  d_in[3];
    const float* W  = (const float*)d_in[4];
    const float* bs = (const float*)d_in[5];
    float* out = (float*)d_out;

    dim3 grid(BATCH, 2, NCHUNK);
    pool_kernel<<<grid, 192>>>(x1, x2, m1, m2);
    gemv_kernel<<<BATCH, 256>>>(W, bs, out);
}